// round 2
// baseline (speedup 1.0000x reference)
#include <cuda_runtime.h>
#include <math.h>

// Problem constants (fixed shapes per reference)
#define NN 100000
#define FF 128
#define CC 40
#define EE 1600000

// Scratch (device globals — no allocation allowed in kernel_launch)
__device__ float g_bufA[(size_t)NN * FF];
__device__ float g_bufB[(size_t)NN * FF];
__device__ float g_bufC[(size_t)NN * FF];
__device__ int   g_off[NN + 1];
__device__ int   g_cursor[NN];
__device__ int   g_ssrc[EE];
__device__ int   g_idx_is64;

// ---------------------------------------------------------------------------
// Dtype sniffer: edge_index may arrive as int64 or int32 (JAX x64 disabled).
// Sample the first half (src row) interpreted as int64; any out-of-range value
// means the buffer is really int32 (two packed indices per 8 bytes).
// Sampling only within [0, E) int64-slots stays in-bounds for both dtypes.
// ---------------------------------------------------------------------------
__global__ void k_detect(const long long* __restrict__ ei, int e, int n) {
    if (threadIdx.x == 0 && blockIdx.x == 0) {
        int is64 = 1;
        long long step = e / 64; if (step < 1) step = 1;
        for (long long i = 0; i < e; i += step) {
            long long v = ei[i];
            if (v < 0 || v >= n) { is64 = 0; break; }
        }
        g_idx_is64 = is64;
    }
}

__device__ __forceinline__ int load_idx(const void* ei, long long elem, int is64) {
    return is64 ? (int)((const long long*)ei)[elem] : ((const int*)ei)[elem];
}

// ---------------------------------------------------------------------------
// CSR construction: histogram -> scan -> scatter
// ---------------------------------------------------------------------------
__global__ void k_zero_off(int n) {
    int i = blockIdx.x * blockDim.x + threadIdx.x;
    if (i <= n) g_off[i] = 0;
}

__global__ void k_hist(const void* __restrict__ ei, int e, int n) {
    int i = blockIdx.x * blockDim.x + threadIdx.x;
    if (i >= e) return;
    int is64 = g_idx_is64;
    int d = load_idx(ei, (long long)e + i, is64);   // dst row lives at offset E
    if ((unsigned)d < (unsigned)n) atomicAdd(&g_off[d + 1], 1);
}

// Single-block inclusive scan over g_off[1..n] (g_off[0] stays 0).
__global__ void k_scan(int n) {
    __shared__ int wsum[32];
    int tid = threadIdx.x, lane = tid & 31, wid = tid >> 5;
    int base = 0;
    for (int start = 1; start <= n; start += 1024) {
        int i = start + tid;
        int v = (i <= n) ? g_off[i] : 0;
        #pragma unroll
        for (int d = 1; d < 32; d <<= 1) {
            int t = __shfl_up_sync(0xffffffffu, v, d);
            if (lane >= d) v += t;
        }
        if (lane == 31) wsum[wid] = v;
        __syncthreads();
        if (wid == 0) {
            int w = wsum[lane];
            #pragma unroll
            for (int d = 1; d < 32; d <<= 1) {
                int t = __shfl_up_sync(0xffffffffu, w, d);
                if (lane >= d) w += t;
            }
            wsum[lane] = w;
        }
        __syncthreads();
        int add = (wid > 0) ? wsum[wid - 1] : 0;
        if (i <= n) g_off[i] = v + add + base;
        int total = wsum[31];
        base += total;
        __syncthreads();
    }
}

__global__ void k_cursor(int n) {
    int i = blockIdx.x * blockDim.x + threadIdx.x;
    if (i < n) g_cursor[i] = g_off[i];
}

__global__ void k_scatter(const void* __restrict__ ei, int e, int n) {
    int i = blockIdx.x * blockDim.x + threadIdx.x;
    if (i >= e) return;
    int is64 = g_idx_is64;
    int s = load_idx(ei, (long long)i, is64);
    int d = load_idx(ei, (long long)e + i, is64);
    if ((unsigned)d < (unsigned)n && (unsigned)s < (unsigned)n) {
        int pos = atomicAdd(&g_cursor[d], 1);
        if (pos < EE) g_ssrc[pos] = s;
    }
}

// ---------------------------------------------------------------------------
// GIN aggregation: out[i] = (1+eps)*h[i] + sum_{j->i} h[j]
// One warp per node, float4 per lane (128 floats = 32 float4).
// ---------------------------------------------------------------------------
__global__ void k_agg(const float* __restrict__ hin, float* __restrict__ hout,
                      const float* __restrict__ epsp, int n) {
    int g = blockIdx.x * blockDim.x + threadIdx.x;
    int node = g >> 5;
    if (node >= n) return;
    int lane = g & 31;
    float sc = 1.0f + *epsp;
    const float4* base = (const float4*)hin;
    float4 acc = __ldg(&base[(size_t)node * 32 + lane]);
    acc.x *= sc; acc.y *= sc; acc.z *= sc; acc.w *= sc;
    int beg = g_off[node], end = g_off[node + 1];
    #pragma unroll 4
    for (int e = beg; e < end; e++) {
        int s = g_ssrc[e];
        float4 v = __ldg(&base[(size_t)s * 32 + lane]);
        acc.x += v.x; acc.y += v.y; acc.z += v.z; acc.w += v.w;
    }
    *(float4*)&hout[(size_t)node * FF + lane * 4] = acc;
}

// ---------------------------------------------------------------------------
// GEMM: out[n,c] = relu(sum_k in[n,k] * w[k,c] + b[c]),  K=128, OUT=128
// Block: 256 threads, 32-row tiles, weights (64KB) + x-tile (16KB) in smem.
// Thread computes a 4x4 register tile. x reads are warp-broadcast LDS,
// w reads are coalesced LDS.128.
// ---------------------------------------------------------------------------
__global__ void k_gemm_relu(const float* __restrict__ in, const float* __restrict__ w,
                            const float* __restrict__ bias, float* __restrict__ out,
                            int nrows) {
    extern __shared__ float sm[];
    float* ws = sm;           // 128*128
    float* xs = sm + 16384;   // 32*128
    int tid = threadIdx.x;
    for (int i = tid; i < 16384; i += 256) ws[i] = w[i];
    int col4 = (tid & 31) * 4;
    int row4 = (tid >> 5) * 4;
    float4 bv = *(const float4*)&bias[col4];
    int ntiles = (nrows + 31) / 32;
    for (int tile = blockIdx.x; tile < ntiles; tile += gridDim.x) {
        int row0 = tile * 32;
        __syncthreads();
        for (int i = tid; i < 4096; i += 256) {
            int r = i >> 7, c = i & 127;
            int gr = row0 + r;
            xs[i] = (gr < nrows) ? in[(size_t)gr * FF + c] : 0.0f;
        }
        __syncthreads();
        float acc[4][4];
        #pragma unroll
        for (int r = 0; r < 4; r++) {
            acc[r][0] = bv.x; acc[r][1] = bv.y; acc[r][2] = bv.z; acc[r][3] = bv.w;
        }
        #pragma unroll 8
        for (int k = 0; k < 128; k++) {
            float4 wv = *(const float4*)&ws[k * 128 + col4];
            float x0 = xs[(row4 + 0) * 128 + k];
            float x1 = xs[(row4 + 1) * 128 + k];
            float x2 = xs[(row4 + 2) * 128 + k];
            float x3 = xs[(row4 + 3) * 128 + k];
            acc[0][0] = fmaf(x0, wv.x, acc[0][0]);
            acc[0][1] = fmaf(x0, wv.y, acc[0][1]);
            acc[0][2] = fmaf(x0, wv.z, acc[0][2]);
            acc[0][3] = fmaf(x0, wv.w, acc[0][3]);
            acc[1][0] = fmaf(x1, wv.x, acc[1][0]);
            acc[1][1] = fmaf(x1, wv.y, acc[1][1]);
            acc[1][2] = fmaf(x1, wv.z, acc[1][2]);
            acc[1][3] = fmaf(x1, wv.w, acc[1][3]);
            acc[2][0] = fmaf(x2, wv.x, acc[2][0]);
            acc[2][1] = fmaf(x2, wv.y, acc[2][1]);
            acc[2][2] = fmaf(x2, wv.z, acc[2][2]);
            acc[2][3] = fmaf(x2, wv.w, acc[2][3]);
            acc[3][0] = fmaf(x3, wv.x, acc[3][0]);
            acc[3][1] = fmaf(x3, wv.y, acc[3][1]);
            acc[3][2] = fmaf(x3, wv.z, acc[3][2]);
            acc[3][3] = fmaf(x3, wv.w, acc[3][3]);
        }
        #pragma unroll
        for (int r = 0; r < 4; r++) {
            int gr = row0 + row4 + r;
            if (gr < nrows) {
                float4 o;
                o.x = fmaxf(acc[r][0], 0.0f);
                o.y = fmaxf(acc[r][1], 0.0f);
                o.z = fmaxf(acc[r][2], 0.0f);
                o.w = fmaxf(acc[r][3], 0.0f);
                *(float4*)&out[(size_t)gr * FF + col4] = o;
            }
        }
    }
}

// ---------------------------------------------------------------------------
// Final layer: out = log_softmax(in @ w4 + b4), K=128, C=40.
// One warp per row; lane owns col=lane and (lane<8) col=32+lane.
// ---------------------------------------------------------------------------
__global__ void k_final(const float* __restrict__ in, const float* __restrict__ w,
                        const float* __restrict__ bias, float* __restrict__ out,
                        int nrows) {
    __shared__ float ws[128 * 40];
    __shared__ float bs[40];
    __shared__ float xrow[8][128];
    int tid = threadIdx.x;
    for (int i = tid; i < 128 * 40; i += 256) ws[i] = w[i];
    if (tid < 40) bs[tid] = bias[tid];
    __syncthreads();
    int wid = tid >> 5, lane = tid & 31;
    for (int row = blockIdx.x * 8 + wid; row < nrows; row += gridDim.x * 8) {
        float4 xv = *(const float4*)&in[(size_t)row * FF + lane * 4];
        *(float4*)&xrow[wid][lane * 4] = xv;
        __syncwarp();
        float a0 = bs[lane];
        float a1 = (lane < 8) ? bs[32 + lane] : 0.0f;
        #pragma unroll 8
        for (int k = 0; k < 128; k++) {
            float xk = xrow[wid][k];
            a0 = fmaf(xk, ws[k * 40 + lane], a0);
            if (lane < 8) a1 = fmaf(xk, ws[k * 40 + 32 + lane], a1);
        }
        float m = a0;
        if (lane < 8) m = fmaxf(m, a1);
        #pragma unroll
        for (int d = 16; d; d >>= 1) m = fmaxf(m, __shfl_xor_sync(0xffffffffu, m, d));
        float s = expf(a0 - m) + ((lane < 8) ? expf(a1 - m) : 0.0f);
        #pragma unroll
        for (int d = 16; d; d >>= 1) s += __shfl_xor_sync(0xffffffffu, s, d);
        float lse = m + logf(s);
        out[(size_t)row * CC + lane] = a0 - lse;
        if (lane < 8) out[(size_t)row * CC + 32 + lane] = a1 - lse;
        __syncwarp();
    }
}

// ---------------------------------------------------------------------------
// Launcher
// ---------------------------------------------------------------------------
extern "C" void kernel_launch(void* const* d_in, const int* in_sizes, int n_in,
                              void* d_out, int out_size) {
    const float* x    = (const float*)d_in[0];
    const void*  ei   = d_in[1];
    const float* eps1 = (const float*)d_in[2];
    const float* w1   = (const float*)d_in[3];
    const float* b1   = (const float*)d_in[4];
    const float* w2   = (const float*)d_in[5];
    const float* b2   = (const float*)d_in[6];
    const float* eps2 = (const float*)d_in[7];
    const float* w3   = (const float*)d_in[8];
    const float* b3   = (const float*)d_in[9];
    const float* w4   = (const float*)d_in[10];
    const float* b4   = (const float*)d_in[11];
    float*       out  = (float*)d_out;

    int N = in_sizes[0] / FF;
    int E = in_sizes[1] / 2;
    if (N > NN) N = NN;
    if (E > EE) E = EE;

    cudaFuncSetAttribute(k_gemm_relu, cudaFuncAttributeMaxDynamicSharedMemorySize,
                         (16384 + 4096) * (int)sizeof(float));

    void *pA = nullptr, *pB = nullptr, *pC = nullptr;
    cudaGetSymbolAddress(&pA, g_bufA);
    cudaGetSymbolAddress(&pB, g_bufB);
    cudaGetSymbolAddress(&pC, g_bufC);
    float* bufA = (float*)pA;
    float* bufB = (float*)pB;
    float* bufC = (float*)pC;

    const int smem_gemm = (16384 + 4096) * (int)sizeof(float);
    const int gemm_grid = 296;  // 2 blocks/SM * 148 SMs

    // Dtype sniff + CSR build (once per launch, reused by both aggregations)
    k_detect<<<1, 32>>>((const long long*)ei, E, N);
    k_zero_off<<<(N + 1 + 255) / 256, 256>>>(N);
    k_hist<<<(E + 255) / 256, 256>>>(ei, E, N);
    k_scan<<<1, 1024>>>(N);
    k_cursor<<<(N + 255) / 256, 256>>>(N);
    k_scatter<<<(E + 255) / 256, 256>>>(ei, E, N);

    // Layer 1: agg -> Lin+ReLU -> Lin+ReLU
    {
        long long tw = (long long)N * 32;
        k_agg<<<(int)((tw + 255) / 256), 256>>>(x, bufA, eps1, N);
    }
    k_gemm_relu<<<gemm_grid, 256, smem_gemm>>>(bufA, w1, b1, bufB, N);
    k_gemm_relu<<<gemm_grid, 256, smem_gemm>>>(bufB, w2, b2, bufC, N);

    // Layer 2: agg -> Lin+ReLU -> Lin -> log_softmax
    {
        long long tw = (long long)N * 32;
        k_agg<<<(int)((tw + 255) / 256), 256>>>(bufC, bufA, eps2, N);
    }
    k_gemm_relu<<<gemm_grid, 256, smem_gemm>>>(bufA, w3, b3, bufB, N);
    k_final<<<(N + 7) / 8, 256>>>(bufB, w4, b4, out, N);
}